// round 4
// baseline (speedup 1.0000x reference)
#include <cuda_runtime.h>
#include <cstdint>

#define HORIZON 30
#define INDIM   384
#define BMAX    65536

typedef unsigned long long ull;

// gi_base scratch: [B, 768] fp32 (192 MB) static device scratch.
__device__ float g_gi[(size_t)BMAX * 768];

__device__ __forceinline__ ull pack2(float lo, float hi) {
    ull r; asm("mov.b64 %0, {%1, %2};" : "=l"(r) : "f"(lo), "f"(hi)); return r;
}
__device__ __forceinline__ void ffma2(ull& d, ull a, ull b) {
    asm("fma.rn.f32x2 %0, %1, %2, %0;" : "+l"(d) : "l"(a), "l"(b));
}
__device__ __forceinline__ void unpack2(ull v, float& lo, float& hi) {
    asm("mov.b64 {%0, %1}, %2;" : "=f"(lo), "=f"(hi) : "l"(v));
}
__device__ __forceinline__ float sigf(float x) {
    return __fdividef(1.f, 1.f + __expf(-x));
}
__device__ __forceinline__ float tanh_fast(float x) {
    float t = __expf(2.f * x);
    return 1.f - __fdividef(2.f, t + 1.f);
}
__device__ __forceinline__ void cpa16(uint32_t s, const void* g) {
    asm volatile("cp.async.cg.shared.global [%0], [%1], 16;" :: "r"(s), "l"(g));
}
#define CPA_COMMIT() asm volatile("cp.async.commit_group;")
#define CPA_WAIT1()  asm volatile("cp.async.wait_group 1;")
#define CPA_WAIT0()  asm volatile("cp.async.wait_group 0;")

// ---------------- shared memory layout (floats) ----------------
#define HT_STRIDE 68
#define HT_SIZE   (256 * HT_STRIDE)          // 17408
#define OFF_HT    0                           // 2 ping-pong buffers
#define OFF_W     (2 * HT_SIZE)              // 34816
#define W_ROWPAD  20                          // 16 k + 4 pad; CF for lane-stride-1 LDS.128
#define W_BUF     (384 * W_ROWPAD)           // 7680 floats / buffer
#define OFF_WMUX  (OFF_W + 2 * W_BUF)        // 50176
#define OFF_WMUY  (OFF_WMUX + 768)
#define OFF_BHH   (OFF_WMUY + 768)
#define OFF_W5    (OFF_BHH + 768)
#define OFF_MUX   (OFF_W5 + 1280)
#define OFF_MUY   (OFF_MUX + 64)
#define SMEM_FLOATS (OFF_MUY + 64)           // 53888 floats = 215552 B

#define NTHR 512

// Stage one 16-k W chunk (24 KB) into buffer (c&1).
// smem row r = g*128 + jrow holds 16 consecutive k for Whh row (g*256 + jb*128 + jrow).
__device__ __forceinline__ void issue_chunk(uint32_t s_w_u32, const float* __restrict__ Whh,
                                            int c, int tid) {
    const int jb = (c >> 4) & 1;
    const int kc = c & 15;
    const uint32_t sbuf = s_w_u32 + (uint32_t)((c & 1) * W_BUF * 4);
    #pragma unroll
    for (int o = 0; o < 3; ++o) {
        int idx = o * NTHR + tid;            // 0..1535
        int r = idx >> 2, q = idx & 3;       // r: smem row (j), q: 16B quad (4 k)
        int g = r >> 7, jr = r & 127;
        const float* gp = Whh + (size_t)(g * 256 + jb * 128 + jr) * 256 + kc * 16 + q * 4;
        cpa16(sbuf + (uint32_t)((r * W_ROWPAD + q * 4) * 4), gp);
    }
}

__global__ void __launch_bounds__(NTHR, 1)
gru_decoder_kernel(const float* __restrict__ zh,  const float* __restrict__ Wh0,
                   const float* __restrict__ bh0, const float* __restrict__ Wih,
                   const float* __restrict__ bih, const float* __restrict__ Whh,
                   const float* __restrict__ bhhg,const float* __restrict__ Wmu,
                   const float* __restrict__ bmu, const float* __restrict__ Wcov,
                   const float* __restrict__ bcov,float* __restrict__ out, int B)
{
    extern __shared__ float sm[];
    float* s_w    = sm + OFF_W;
    float* s_wmux = sm + OFF_WMUX;
    float* s_wmuy = sm + OFF_WMUY;
    float* s_bhh  = sm + OFF_BHH;
    float* s_w5   = sm + OFF_W5;
    float* s_mux  = sm + OFF_MUX;
    float* s_muy  = sm + OFF_MUY;

    const int tid = threadIdx.x;
    const int jl  = tid & 63;          // j lane: covers j = jl and jl+64 within a 128-j block
    const int mg  = tid >> 6;          // 0..7
    const int m0  = mg * 8;            // 8 batch rows per thread; warp-uniform -> h bcast
    const int b0  = blockIdx.x * 64;

    const uint32_t s_w_u32 = (uint32_t)__cvta_generic_to_shared(s_w);

    // ---- one-time small-weight staging ----
    for (int i = tid; i < 768; i += NTHR) {
        s_wmux[i] = Wih[(size_t)i * 386 + 384];
        s_wmuy[i] = Wih[(size_t)i * 386 + 385];
        s_bhh[i]  = bhhg[i];
    }
    for (int i = tid; i < 512; i += NTHR) s_w5[i] = Wmu[i];
    for (int i = tid; i < 768; i += NTHR) s_w5[512 + i] = Wcov[i];
    if (tid < 64) { s_mux[tid] = 0.f; s_muy[tid] = 0.f; }

    // ================= PRECOMPUTE: h0 (buf 0, transposed) and gi_base (global) ==========
    {
        const int tx4 = tid & 15, ty4 = tid >> 4;   // ty4: 0..31
        const int j04 = tx4 * 4, m04 = ty4 * 2;     // m-tile 2, j-tile 4
        float* s_zhT = s_w;          // [64 k][68]
        float* s_wtp = s_w + 4352;   // [64 k][68]

        for (int jb = 0; jb < 16; ++jb) {
            ull acc[2][2];
            acc[0][0]=0ull; acc[0][1]=0ull; acc[1][0]=0ull; acc[1][1]=0ull;

            for (int kc = 0; kc < 6; ++kc) {
                __syncthreads();
                #pragma unroll
                for (int it = 0; it < 8; ++it) {
                    int idx = it * NTHR + tid;
                    int kk = idx & 63, rr = idx >> 6;
                    s_zhT[kk * 68 + rr] = zh[(size_t)(b0 + rr) * INDIM + kc * 64 + kk];
                    int jp = jb * 64 + rr;
                    const float* wrow = (jp < 256) ? (Wh0 + (size_t)jp * 384)
                                                   : (Wih + (size_t)(jp - 256) * 386);
                    s_wtp[kk * 68 + rr] = wrow[kc * 64 + kk];
                }
                __syncthreads();
                #pragma unroll 8
                for (int k = 0; k < 64; ++k) {
                    float2 hv = *(const float2*)&s_zhT[k * 68 + m04];
                    ull w0 = *(const ull*)&s_wtp[k * 68 + j04];
                    ull w1 = *(const ull*)&s_wtp[k * 68 + j04 + 2];
                    ull a0 = pack2(hv.x, hv.x), a1 = pack2(hv.y, hv.y);
                    ffma2(acc[0][0], a0, w0); ffma2(acc[0][1], a0, w1);
                    ffma2(acc[1][0], a1, w0); ffma2(acc[1][1], a1, w1);
                }
            }
            float v[2][4];
            #pragma unroll
            for (int m = 0; m < 2; ++m) {
                unpack2(acc[m][0], v[m][0], v[m][1]);
                unpack2(acc[m][1], v[m][2], v[m][3]);
            }
            if (jb < 4) {
                #pragma unroll
                for (int jj = 0; jj < 4; ++jj) {
                    int j = jb * 64 + j04 + jj;
                    float b = bh0[j];
                    *(float2*)&sm[OFF_HT + (size_t)j * HT_STRIDE + m04] =
                        make_float2(v[0][jj] + b, v[1][jj] + b);
                }
            } else {
                int gcol = jb * 64 - 256 + j04;
                float4 bb = *(const float4*)&bih[gcol];
                #pragma unroll
                for (int m = 0; m < 2; ++m) {
                    *(float4*)&g_gi[(size_t)(b0 + m04 + m) * 768 + gcol] =
                        make_float4(v[m][0] + bb.x, v[m][1] + bb.y, v[m][2] + bb.z, v[m][3] + bb.w);
                }
            }
        }
        __syncthreads();
    }

    const size_t covbase = (size_t)B * HORIZON * 2;

    // Prime the W pipeline
    issue_chunk(s_w_u32, Whh, 0, tid);
    CPA_COMMIT();

    // ================= 30-step GRU recurrence =================
    int cur = 0;
    #pragma unroll 1
    for (int t = 0; t < HORIZON; ++t) {
        float* hcur = sm + OFF_HT + cur * HT_SIZE;
        float* hnxt = sm + OFF_HT + (1 - cur) * HT_SIZE;

        #pragma unroll 1
        for (int jb = 0; jb < 2; ++jb) {
            const int jbase = jb * 128 + jl;

            // acc[gate][jhalf][mpair], seeded with b_hh
            ull aR[2][4], aZ[2][4], aN[2][4];
            #pragma unroll
            for (int jh = 0; jh < 2; ++jh) {
                int j = jbase + 64 * jh;
                ull br = pack2(s_bhh[j], s_bhh[j]);
                ull bz = pack2(s_bhh[256 + j], s_bhh[256 + j]);
                ull bn = pack2(s_bhh[512 + j], s_bhh[512 + j]);
                #pragma unroll
                for (int mp = 0; mp < 4; ++mp) { aR[jh][mp]=br; aZ[jh][mp]=bz; aN[jh][mp]=bn; }
            }

            #pragma unroll 1
            for (int kc = 0; kc < 16; ++kc) {
                const int c = jb * 16 + kc;
                issue_chunk(s_w_u32, Whh, (c + 1) & 31, tid);
                CPA_COMMIT();
                CPA_WAIT1();
                __syncthreads();

                const float* wb  = s_w + (c & 1) * W_BUF;
                const float* hch = hcur + (size_t)(kc * 16) * HT_STRIDE + m0;

                #pragma unroll
                for (int kg = 0; kg < 4; ++kg) {
                    // 6 LDS.128: W quads (4 k) for (3 gates x 2 j-halves); CF (stride 20)
                    float4 w4[3][2];
                    #pragma unroll
                    for (int g = 0; g < 3; ++g)
                        #pragma unroll
                        for (int jh = 0; jh < 2; ++jh)
                            w4[g][jh] = *(const float4*)&wb[(g * 128 + jl + 64 * jh) * W_ROWPAD + kg * 4];
                    #pragma unroll
                    for (int kk = 0; kk < 4; ++kk) {
                        const float* hr = hch + (size_t)(kg * 4 + kk) * HT_STRIDE;
                        ulonglong2 q0 = *(const ulonglong2*)hr;        // m pairs 0..3
                        ulonglong2 q1 = *(const ulonglong2*)(hr + 4);  // m pairs 4..7
                        #pragma unroll
                        for (int jh = 0; jh < 2; ++jh) {
                            float wr = ((const float*)&w4[0][jh])[kk];
                            float wz = ((const float*)&w4[1][jh])[kk];
                            float wn = ((const float*)&w4[2][jh])[kk];
                            ull dr = pack2(wr, wr), dz = pack2(wz, wz), dn = pack2(wn, wn);
                            ffma2(aR[jh][0], q0.x, dr); ffma2(aR[jh][1], q0.y, dr);
                            ffma2(aR[jh][2], q1.x, dr); ffma2(aR[jh][3], q1.y, dr);
                            ffma2(aZ[jh][0], q0.x, dz); ffma2(aZ[jh][1], q0.y, dz);
                            ffma2(aZ[jh][2], q1.x, dz); ffma2(aZ[jh][3], q1.y, dz);
                            ffma2(aN[jh][0], q0.x, dn); ffma2(aN[jh][1], q0.y, dn);
                            ffma2(aN[jh][2], q1.x, dn); ffma2(aN[jh][3], q1.y, dn);
                        }
                    }
                }
                __syncthreads();   // all reads of buf (c&1) done before it is re-filled
            }

            // ---- gate epilogue for this j-block: 2 j per thread, 8 m each ----
            #pragma unroll
            for (int jh = 0; jh < 2; ++jh) {
                const int j = jbase + 64 * jh;
                float fr[8], fz[8], fn[8];
                #pragma unroll
                for (int mp = 0; mp < 4; ++mp) {
                    unpack2(aR[jh][mp], fr[2*mp], fr[2*mp+1]);
                    unpack2(aZ[jh][mp], fz[2*mp], fz[2*mp+1]);
                    unpack2(aN[jh][mp], fn[2*mp], fn[2*mp+1]);
                }
                float wxr = s_wmux[j], wxz = s_wmux[256 + j], wxn = s_wmux[512 + j];
                float wyr = s_wmuy[j], wyz = s_wmuy[256 + j], wyn = s_wmuy[512 + j];

                const float* hp = &hcur[(size_t)j * HT_STRIDE + m0];
                float4 o0 = *(const float4*)hp;
                float4 o1 = *(const float4*)(hp + 4);
                float ho[8] = {o0.x,o0.y,o0.z,o0.w,o1.x,o1.y,o1.z,o1.w};

                float hnew[8];
                #pragma unroll
                for (int m = 0; m < 8; ++m) {
                    const float* gp = &g_gi[(size_t)(b0 + m0 + m) * 768 + j];
                    float gr = gp[0], gz = gp[256], gn = gp[512];
                    float mx = s_mux[m0 + m], my = s_muy[m0 + m];
                    float r  = sigf(gr + mx * wxr + my * wyr + fr[m]);
                    float z  = sigf(gz + mx * wxz + my * wyz + fz[m]);
                    float n  = tanh_fast(gn + mx * wxn + my * wyn + r * fn[m]);
                    hnew[m] = (1.f - z) * n + z * ho[m];
                }
                float* hq = &hnxt[(size_t)j * HT_STRIDE + m0];
                *(float4*)hq       = make_float4(hnew[0], hnew[1], hnew[2], hnew[3]);
                *(float4*)(hq + 4) = make_float4(hnew[4], hnew[5], hnew[6], hnew[7]);
            }
        } // jb

        __syncthreads();   // hnxt fully written

        // ---- mu / cov: 5 dots of length 256 per batch row (320 tasks) ----
        if (tid < 320) {
            int o = tid >> 6; int m = tid & 63;
            const float* wrow = &s_w5[o * 256];
            const float* hc = hnxt + m;
            float a0 = 0.f, a1 = 0.f, a2 = 0.f, a3 = 0.f;
            #pragma unroll 4
            for (int k = 0; k < 256; k += 4) {
                a0 += hc[(size_t)(k    ) * HT_STRIDE] * wrow[k    ];
                a1 += hc[(size_t)(k + 1) * HT_STRIDE] * wrow[k + 1];
                a2 += hc[(size_t)(k + 2) * HT_STRIDE] * wrow[k + 2];
                a3 += hc[(size_t)(k + 3) * HT_STRIDE] * wrow[k + 3];
            }
            float acc = (a0 + a1) + (a2 + a3);
            size_t idx2 = ((size_t)(b0 + m) * HORIZON + t);
            if (o == 0) {
                float vv = acc + bmu[0]; out[idx2 * 2]     = vv; s_mux[m] = vv;
            } else if (o == 1) {
                float vv = acc + bmu[1]; out[idx2 * 2 + 1] = vv; s_muy[m] = vv;
            } else if (o == 2) {
                float vv = fminf(fmaxf(acc + bcov[0], 0.2f), 1.0f);
                out[covbase + idx2 * 4]     = vv;
            } else if (o == 3) {
                float vv = fminf(fmaxf(acc + bcov[1], -0.1f), 0.1f);
                out[covbase + idx2 * 4 + 1] = vv;
                out[covbase + idx2 * 4 + 2] = vv;
            } else {
                float vv = fminf(fmaxf(acc + bcov[2], 0.2f), 1.0f);
                out[covbase + idx2 * 4 + 3] = vv;
            }
        }
        cur ^= 1;
        // next step's first in-kc __syncthreads orders s_mux/s_muy + h buffers
    }

    CPA_WAIT0();   // drain final speculative prefetch
}

extern "C" void kernel_launch(void* const* d_in, const int* in_sizes, int n_in,
                              void* d_out, int out_size) {
    const float* zh   = (const float*)d_in[0];
    const float* Wh0  = (const float*)d_in[1];
    const float* bh0  = (const float*)d_in[2];
    const float* Wih  = (const float*)d_in[3];
    const float* bih  = (const float*)d_in[4];
    const float* Whh  = (const float*)d_in[5];
    const float* bhh  = (const float*)d_in[6];
    const float* Wmu  = (const float*)d_in[7];
    const float* bmu  = (const float*)d_in[8];
    const float* Wcov = (const float*)d_in[9];
    const float* bcov = (const float*)d_in[10];
    float* out = (float*)d_out;

    int B = in_sizes[0] / INDIM;
    cudaFuncSetAttribute(gru_decoder_kernel,
                         cudaFuncAttributeMaxDynamicSharedMemorySize, SMEM_FLOATS * 4);
    gru_decoder_kernel<<<B / 64, NTHR, SMEM_FLOATS * 4>>>(
        zh, Wh0, bh0, Wih, bih, Whh, bhh, Wmu, bmu, Wcov, bcov, out, B);
}